// round 16
// baseline (speedup 1.0000x reference)
#include <cuda_runtime.h>
#include <cuda_bf16.h>
#include <cstdint>
#include <cstddef>

#define HIDN  3072
#define LTOT  2304
#define IMGN  2048
#define NHEAD 24
#define HD    128
#define REFN  512
#define QKV3  9216
#define NN1   21504
#define CATN  15360

// ---------------- scratch (device globals; no allocation) ----------------
static __device__ float g_modp[8 * QKV3];
static __device__ float g_mod[QKV3];                          // shift | scl | gate
static __device__ float g_xmod[(size_t)LTOT * HIDN];          // tf32-rounded
static __device__ float g_qkv[(size_t)LTOT * QKV3];
static __device__ float g_q[(size_t)NHEAD * LTOT * HD];       // tf32-rounded
static __device__ float g_k[(size_t)NHEAD * LTOT * HD];       // tf32-rounded
static __device__ float g_v[(size_t)NHEAD * LTOT * HD];       // tf32-rounded
static __device__ float g_rkraw[(size_t)REFN * HIDN];
static __device__ float g_rvraw[(size_t)REFN * HIDN];         // tf32-rounded
static __device__ float g_rk[(size_t)NHEAD * REFN * HD];      // tf32-rounded
static __device__ float g_cat[(size_t)LTOT * CATN];           // tf32-rounded [attn | gelu(mlp)]
static __device__ float g_w1r[(size_t)HIDN * NN1];            // tf32-rounded w1
static __device__ float g_w2r[(size_t)CATN * HIDN];           // tf32-rounded w2

// ---------------- helpers ----------------
__device__ __forceinline__ float tf32r(float x) {
    unsigned u;
    asm("cvt.rna.tf32.f32 %0, %1;" : "=r"(u) : "f"(x));
    return __uint_as_float(u);
}

__device__ __forceinline__ void mma8(float c[4], const unsigned a[4], const unsigned b[2]) {
    asm volatile(
        "mma.sync.aligned.m16n8k8.row.col.f32.tf32.tf32.f32 "
        "{%0,%1,%2,%3}, {%4,%5,%6,%7}, {%8,%9}, {%0,%1,%2,%3};\n"
        : "+f"(c[0]), "+f"(c[1]), "+f"(c[2]), "+f"(c[3])
        : "r"(a[0]), "r"(a[1]), "r"(a[2]), "r"(a[3]), "r"(b[0]), "r"(b[1]));
}

__device__ __forceinline__ void cp16(const float* smem_dst, const float* gsrc) {
    unsigned s = (unsigned)__cvta_generic_to_shared(smem_dst);
    asm volatile("cp.async.cg.shared.global [%0], [%1], 16;" :: "r"(s), "l"(gsrc));
}
#define CP_COMMIT() asm volatile("cp.async.commit_group;")
#define CP_WAIT0()  asm volatile("cp.async.wait_group 0;")
#define CP_WAIT1()  asm volatile("cp.async.wait_group 1;")

__device__ __forceinline__ float gelu_t(float v) {
    return 0.5f * v * (1.0f + tanhf(0.7978845608028654f * (v + 0.044715f * v * v * v)));
}

// ---------------- weight pre-round to tf32 ----------------
__global__ void round_w(const float* __restrict__ src, float* __restrict__ dst, size_t n4) {
    size_t stride = (size_t)gridDim.x * blockDim.x;
    for (size_t i = blockIdx.x * (size_t)blockDim.x + threadIdx.x; i < n4; i += stride) {
        float4 v = *(const float4*)(src + i * 4);
        v.x = tf32r(v.x); v.y = tf32r(v.y); v.z = tf32r(v.z); v.w = tf32r(v.w);
        *(float4*)(dst + i * 4) = v;
    }
}

// ---------------- mod = silu(vec) @ w_mod + b_mod (split-K) ----------------
__global__ void mod_gemv(const float* __restrict__ vec, const float* __restrict__ w) {
    __shared__ float sv2[384];
    int ky = blockIdx.y;
    int k0 = ky * 384;
    for (int i = threadIdx.x; i < 384; i += 256) {
        float xx = vec[k0 + i];
        sv2[i] = xx / (1.f + __expf(-xx));
    }
    __syncthreads();
    int c = blockIdx.x * 256 + threadIdx.x;
    const float* wp = w + (size_t)k0 * QKV3 + c;
    float acc = 0.f;
#pragma unroll 8
    for (int k = 0; k < 384; ++k) acc += sv2[k] * wp[(size_t)k * QKV3];
    g_modp[ky * QKV3 + c] = acc;
}

__global__ void mod_reduce(const float* __restrict__ bmod) {
    int c = blockIdx.x * 256 + threadIdx.x;
    float a = bmod[c];
#pragma unroll
    for (int ky = 0; ky < 8; ky++) a += g_modp[ky * QKV3 + c];
    g_mod[c] = a;
}

// ---------------- x_mod = layernorm(x)*(1+scl)+shift  (tf32-rounded) ----------------
__global__ void ln_mod_kernel(const float* __restrict__ x) {
    __shared__ float sh[16];
    int row = blockIdx.x;
    const float* xp = x + (size_t)row * HIDN;
    float4 v[3];
    float s = 0.f, q = 0.f;
#pragma unroll
    for (int i = 0; i < 3; i++) {
        v[i] = *(const float4*)(xp + (threadIdx.x + i * 256) * 4);
        s += v[i].x + v[i].y + v[i].z + v[i].w;
        q += v[i].x * v[i].x + v[i].y * v[i].y + v[i].z * v[i].z + v[i].w * v[i].w;
    }
#pragma unroll
    for (int o = 16; o; o >>= 1) {
        s += __shfl_xor_sync(0xffffffffu, s, o);
        q += __shfl_xor_sync(0xffffffffu, q, o);
    }
    int wid = threadIdx.x >> 5;
    if ((threadIdx.x & 31) == 0) { sh[wid] = s; sh[8 + wid] = q; }
    __syncthreads();
    if (threadIdx.x == 0) {
        float a = 0.f, b = 0.f;
#pragma unroll
        for (int i = 0; i < 8; i++) { a += sh[i]; b += sh[8 + i]; }
        sh[0] = a; sh[8] = b;
    }
    __syncthreads();
    float mean = sh[0] * (1.f / HIDN);
    float var  = sh[8] * (1.f / HIDN) - mean * mean;
    float inv  = rsqrtf(var + 1e-6f);
#pragma unroll
    for (int i = 0; i < 3; i++) {
        int c = (threadIdx.x + i * 256) * 4;
        float4 o;
        o.x = tf32r((v[i].x - mean) * inv * (1.f + g_mod[HIDN + c + 0]) + g_mod[c + 0]);
        o.y = tf32r((v[i].y - mean) * inv * (1.f + g_mod[HIDN + c + 1]) + g_mod[c + 1]);
        o.z = tf32r((v[i].z - mean) * inv * (1.f + g_mod[HIDN + c + 2]) + g_mod[c + 2]);
        o.w = tf32r((v[i].w - mean) * inv * (1.f + g_mod[HIDN + c + 3]) + g_mod[c + 3]);
        *(float4*)(g_xmod + (size_t)row * HIDN + c) = o;
    }
}

// ---------------- lin1 GEMM: 128x256 tile, warp tile 64x64, 3-stage, 1 sync/tile ----------------
__global__ void __launch_bounds__(256, 1) gemm_lin1(
    const float* __restrict__ bias, int M, int N, int K) {
    extern __shared__ float ds[];
    const int BUF = 13056;  // 128*36 + 32*264 floats per stage
    const float* A = g_xmod;
    const float* B = g_w1r;

    int tid = threadIdx.x, lane = tid & 31, wid = tid >> 5;
    int g = lane >> 2, t = lane & 3;
    int wm = wid >> 2, wn = wid & 3;
    int bm = blockIdx.x * 128, bn = blockIdx.y * 256;

    float c[4][8][4];
#pragma unroll
    for (int mf = 0; mf < 4; mf++)
#pragma unroll
        for (int nf = 0; nf < 8; nf++)
#pragma unroll
            for (int i = 0; i < 4; i++) c[mf][nf][i] = 0.f;

    const float* Ap = A + (size_t)bm * K;
    const float* Bp = B + bn;

    auto issue = [&](int kt, int buf) {
        int k0 = kt << 5;
        float* sA = ds + buf * BUF;
        float* sB = sA + 4608;
#pragma unroll
        for (int i = 0; i < 4; i++) {
            int f = tid + i * 256;
            int r = f >> 3, cc = f & 7;
            cp16(sA + r * 36 + cc * 4, Ap + (size_t)r * K + k0 + cc * 4);
        }
#pragma unroll
        for (int i = 0; i < 8; i++) {
            int f = tid + i * 256;
            int r = f >> 6, cc = f & 63;
            cp16(sB + r * 264 + cc * 4, Bp + (size_t)(k0 + r) * N + cc * 4);
        }
        CP_COMMIT();
    };

    int nt = K >> 5;  // 96
    issue(0, 0); issue(1, 1);
    for (int it = 0; it < nt; it++) {
        if (it == nt - 1) CP_WAIT0(); else CP_WAIT1();
        __syncthreads();
        if (it + 2 < nt) issue(it + 2, (it + 2) % 3);
        float* sA = ds + (it % 3) * BUF;
        float* sB = sA + 4608;
#pragma unroll
        for (int ks = 0; ks < 4; ks++) {
            int kk = ks * 8;
            unsigned a[4][4], b[8][2];
#pragma unroll
            for (int mf = 0; mf < 4; mf++) {
                int rb = wm * 64 + mf * 16 + g;
                a[mf][0] = __float_as_uint(sA[rb * 36 + kk + t]);
                a[mf][1] = __float_as_uint(sA[(rb + 8) * 36 + kk + t]);
                a[mf][2] = __float_as_uint(sA[rb * 36 + kk + t + 4]);
                a[mf][3] = __float_as_uint(sA[(rb + 8) * 36 + kk + t + 4]);
            }
#pragma unroll
            for (int nf = 0; nf < 8; nf++) {
                int cb = wn * 64 + nf * 8 + g;
                b[nf][0] = __float_as_uint(sB[(kk + t) * 264 + cb]);
                b[nf][1] = __float_as_uint(sB[(kk + t + 4) * 264 + cb]);
            }
#pragma unroll
            for (int mf = 0; mf < 4; mf++)
#pragma unroll
                for (int nf = 0; nf < 8; nf++) mma8(c[mf][nf], a[mf], b[nf]);
        }
    }

#pragma unroll
    for (int mf = 0; mf < 4; mf++)
#pragma unroll
        for (int nf = 0; nf < 8; nf++) {
            int row = bm + wm * 64 + mf * 16 + g;
            int col = bn + wn * 64 + nf * 8 + 2 * t;
            float2 b2 = *(const float2*)(bias + col);
            float2 v0 = make_float2(c[mf][nf][0] + b2.x, c[mf][nf][1] + b2.y);
            float2 v1 = make_float2(c[mf][nf][2] + b2.x, c[mf][nf][3] + b2.y);
            if (col < QKV3) {
                *(float2*)(g_qkv + (size_t)row * QKV3 + col) = v0;
                *(float2*)(g_qkv + (size_t)(row + 8) * QKV3 + col) = v1;
            } else {
                int cc = HIDN + (col - QKV3);
                *(float2*)(g_cat + (size_t)row * CATN + cc) =
                    make_float2(tf32r(gelu_t(v0.x)), tf32r(gelu_t(v0.y)));
                *(float2*)(g_cat + (size_t)(row + 8) * CATN + cc) =
                    make_float2(tf32r(gelu_t(v1.x)), tf32r(gelu_t(v1.y)));
            }
        }
}

// ---------------- out GEMM: 128x96 tile (wave-quantization fix), 3-stage, 2 CTAs/SM ----------------
// grid (18, 32) = 576 CTAs -> 1.95 waves at 296 concurrent (vs 1.46 at 128x128).
// Warp tile 32x48 (4m x 2n), c[2][6][4]. B smem stride 104 -> banks t*8+g, conflict-free.
__global__ void __launch_bounds__(256, 2) gemm_out(
    const float* __restrict__ bias, float* __restrict__ O,
    const float* __restrict__ resid, int M, int N, int K) {
    extern __shared__ float ds[];
    const int BUF = 7936;  // 128*36 + 32*104 floats per stage
    const float* A = g_cat;
    const float* B = g_w2r;

    int tid = threadIdx.x, lane = tid & 31, wid = tid >> 5;
    int g = lane >> 2, t = lane & 3;
    int wm = wid >> 1, wn = wid & 1;
    int bm = blockIdx.x * 128, bn = blockIdx.y * 96;

    float c[2][6][4];
#pragma unroll
    for (int mf = 0; mf < 2; mf++)
#pragma unroll
        for (int nf = 0; nf < 6; nf++)
#pragma unroll
            for (int i = 0; i < 4; i++) c[mf][nf][i] = 0.f;

    const float* Ap = A + (size_t)bm * K;
    const float* Bp = B + bn;

    auto issue = [&](int kt, int buf) {
        int k0 = kt << 5;
        float* sA = ds + buf * BUF;
        float* sB = sA + 4608;
#pragma unroll
        for (int i = 0; i < 4; i++) {
            int f = tid + i * 256;
            int r = f >> 3, cc = f & 7;
            cp16(sA + r * 36 + cc * 4, Ap + (size_t)r * K + k0 + cc * 4);
        }
#pragma unroll
        for (int i = 0; i < 3; i++) {           // 32 rows x 24 float4 = 768
            int f = tid + i * 256;
            int r = f / 24, cc = f % 24;
            cp16(sB + r * 104 + cc * 4, Bp + (size_t)(k0 + r) * N + cc * 4);
        }
        CP_COMMIT();
    };

    int nt = K >> 5;  // 480
    issue(0, 0); issue(1, 1);
    for (int it = 0; it < nt; it++) {
        if (it == nt - 1) CP_WAIT0(); else CP_WAIT1();
        __syncthreads();
        if (it + 2 < nt) issue(it + 2, (it + 2) % 3);
        float* sA = ds + (it % 3) * BUF;
        float* sB = sA + 4608;
#pragma unroll
        for (int ks = 0; ks < 4; ks++) {
            int kk = ks * 8;
            unsigned a[2][4], b[6][2];
#pragma unroll
            for (int mf = 0; mf < 2; mf++) {
                int rb = wm * 32 + mf * 16 + g;
                a[mf][0] = __float_as_uint(sA[rb * 36 + kk + t]);
                a[mf][1] = __float_as_uint(sA[(rb + 8) * 36 + kk + t]);
                a[mf][2] = __float_as_uint(sA[rb * 36 + kk + t + 4]);
                a[mf][3] = __float_as_uint(sA[(rb + 8) * 36 + kk + t + 4]);
            }
#pragma unroll
            for (int nf = 0; nf < 6; nf++) {
                int cb = wn * 48 + nf * 8 + g;
                b[nf][0] = __float_as_uint(sB[(kk + t) * 104 + cb]);
                b[nf][1] = __float_as_uint(sB[(kk + t + 4) * 104 + cb]);
            }
#pragma unroll
            for (int mf = 0; mf < 2; mf++)
#pragma unroll
                for (int nf = 0; nf < 6; nf++) mma8(c[mf][nf], a[mf], b[nf]);
        }
    }

#pragma unroll
    for (int mf = 0; mf < 2; mf++)
#pragma unroll
        for (int nf = 0; nf < 6; nf++) {
            int row = bm + wm * 32 + mf * 16 + g;
            int col = bn + wn * 48 + nf * 8 + 2 * t;
            float2 b2 = *(const float2*)(bias + col);
            float2 v0 = make_float2(c[mf][nf][0] + b2.x, c[mf][nf][1] + b2.y);
            float2 v1 = make_float2(c[mf][nf][2] + b2.x, c[mf][nf][3] + b2.y);
            float2 gt = *(const float2*)(g_mod + 2 * HIDN + col);
            size_t i0 = (size_t)row * HIDN + col;
            size_t i1 = (size_t)(row + 8) * HIDN + col;
            float2 r0 = *(const float2*)(resid + i0);
            float2 r1 = *(const float2*)(resid + i1);
            *(float2*)(O + i0) = make_float2(r0.x + gt.x * v0.x, r0.y + gt.y * v0.y);
            *(float2*)(O + i1) = make_float2(r1.x + gt.x * v1.x, r1.y + gt.y * v1.y);
        }
}

// ---------------- register-path TF32 GEMM (EPI 1 = ref_k, 2 = ref_v) ----------------
template <int EPI>
__global__ void __launch_bounds__(256) gemm_tf32(
    const float* __restrict__ Aarg, const float* __restrict__ B,
    const float* __restrict__ bias, int M, int N, int K) {
    __shared__ float sA[128 * 36];
    __shared__ float sB[32 * 136];
    const float* A = Aarg;

    int tid = threadIdx.x, lane = tid & 31, wid = tid >> 5;
    int g = lane >> 2, t = lane & 3;
    int wm = wid >> 1, wn = wid & 1;
    int bm = blockIdx.x * 128, bn = blockIdx.y * 128;

    float c[2][8][4];
#pragma unroll
    for (int mf = 0; mf < 2; mf++)
#pragma unroll
        for (int nf = 0; nf < 8; nf++)
#pragma unroll
            for (int i = 0; i < 4; i++) c[mf][nf][i] = 0.f;

    const float* Ap = A + (size_t)bm * K;
    const float* Bp = B + bn;

    for (int k0 = 0; k0 < K; k0 += 32) {
        __syncthreads();
#pragma unroll
        for (int i = 0; i < 4; i++) {
            int f = tid + i * 256;
            int r = f >> 3, cc = f & 7;
            float4 v = *(const float4*)(Ap + (size_t)r * K + k0 + cc * 4);
            float* d = sA + r * 36 + cc * 4;
            d[0] = tf32r(v.x); d[1] = tf32r(v.y); d[2] = tf32r(v.z); d[3] = tf32r(v.w);
        }
#pragma unroll
        for (int i = 0; i < 4; i++) {
            int f = tid + i * 256;
            int r = f >> 5, cc = f & 31;
            float4 v = *(const float4*)(Bp + (size_t)(k0 + r) * N + cc * 4);
            float* d = sB + r * 136 + cc * 4;
            d[0] = tf32r(v.x); d[1] = tf32r(v.y); d[2] = tf32r(v.z); d[3] = tf32r(v.w);
        }
        __syncthreads();
#pragma unroll
        for (int ks = 0; ks < 4; ks++) {
            int kk = ks * 8;
            unsigned a[2][4], b[8][2];
#pragma unroll
            for (int mf = 0; mf < 2; mf++) {
                int rb = wm * 32 + mf * 16 + g;
                a[mf][0] = __float_as_uint(sA[rb * 36 + kk + t]);
                a[mf][1] = __float_as_uint(sA[(rb + 8) * 36 + kk + t]);
                a[mf][2] = __float_as_uint(sA[rb * 36 + kk + t + 4]);
                a[mf][3] = __float_as_uint(sA[(rb + 8) * 36 + kk + t + 4]);
            }
#pragma unroll
            for (int nf = 0; nf < 8; nf++) {
                int cb = wn * 64 + nf * 8 + g;
                b[nf][0] = __float_as_uint(sB[(kk + t) * 136 + cb]);
                b[nf][1] = __float_as_uint(sB[(kk + t + 4) * 136 + cb]);
            }
#pragma unroll
            for (int mf = 0; mf < 2; mf++)
#pragma unroll
                for (int nf = 0; nf < 8; nf++) mma8(c[mf][nf], a[mf], b[nf]);
        }
    }

#pragma unroll
    for (int mf = 0; mf < 2; mf++)
#pragma unroll
        for (int nf = 0; nf < 8; nf++)
#pragma unroll
            for (int i = 0; i < 4; i++) {
                int row = bm + wm * 32 + mf * 16 + g + ((i >> 1) ? 8 : 0);
                int col = bn + wn * 64 + nf * 8 + t * 2 + (i & 1);
                float v = c[mf][nf][i] + bias[col];
                if (EPI == 1) g_rkraw[(size_t)row * HIDN + col] = v;
                else          g_rvraw[(size_t)row * HIDN + col] = tf32r(v);
            }
}

// ---------------- qkv prep: rmsnorm + rope + relayout (tf32-rounded) ----------------
__global__ void qkvprep(const float* __restrict__ qn_w, const float* __restrict__ kn_w,
                        const float* __restrict__ cosp, const float* __restrict__ sinp) {
    int h = blockIdx.x, row = blockIdx.y, t = threadIdx.x;
    const float* base = g_qkv + (size_t)row * QKV3 + h * HD;
    float q = base[t], k = base[HIDN + t], v = base[2 * HIDN + t];
    __shared__ float red[8];
    float sq = q * q, sk = k * k;
#pragma unroll
    for (int o = 16; o; o >>= 1) {
        sq += __shfl_xor_sync(0xffffffffu, sq, o);
        sk += __shfl_xor_sync(0xffffffffu, sk, o);
    }
    int w = t >> 5;
    if ((t & 31) == 0) { red[w] = sq; red[4 + w] = sk; }
    __syncthreads();
    float ssq = red[0] + red[1] + red[2] + red[3];
    float ssk = red[4] + red[5] + red[6] + red[7];
    q *= rsqrtf(ssq * (1.f / HD) + 1e-6f) * qn_w[t];
    k *= rsqrtf(ssk * (1.f / HD) + 1e-6f) * kn_w[t];
    if (row < IMGN) {
        float cv = cosp[row * 64 + (t >> 1)], sv = sinp[row * 64 + (t >> 1)];
        float qo = __shfl_xor_sync(0xffffffffu, q, 1);
        float ko = __shfl_xor_sync(0xffffffffu, k, 1);
        if ((t & 1) == 0) { q = q * cv - qo * sv; k = k * cv - ko * sv; }
        else              { q = qo * sv + q * cv; k = ko * sv + k * cv; }
    }
    size_t oidx = ((size_t)h * LTOT + row) * HD + t;
    g_q[oidx] = tf32r(q); g_k[oidx] = tf32r(k); g_v[oidx] = tf32r(v);
}

// ---------------- ref_k prep: rmsnorm + rope (tf32-rounded) ----------------
__global__ void refprep(const float* __restrict__ ref_kn_w,
                        const float* __restrict__ rcos, const float* __restrict__ rsin) {
    int h = blockIdx.x, row = blockIdx.y, t = threadIdx.x;
    float k = g_rkraw[(size_t)row * HIDN + h * HD + t];
    __shared__ float red[4];
    float sk = k * k;
#pragma unroll
    for (int o = 16; o; o >>= 1) sk += __shfl_xor_sync(0xffffffffu, sk, o);
    int w = t >> 5;
    if ((t & 31) == 0) red[w] = sk;
    __syncthreads();
    float ssk = red[0] + red[1] + red[2] + red[3];
    k *= rsqrtf(ssk * (1.f / HD) + 1e-6f) * ref_kn_w[t];
    float cv = rcos[row * 64 + (t >> 1)], sv = rsin[row * 64 + (t >> 1)];
    float ko = __shfl_xor_sync(0xffffffffu, k, 1);
    if ((t & 1) == 0) k = k * cv - ko * sv;
    else              k = ko * sv + k * cv;
    g_rk[((size_t)h * REFN + row) * HD + t] = tf32r(k);
}

// ---------------- fused flash attention: 128-row q tiles, 8 warps ----------------
// smem floats: [0..16895] 2-stage K|V (also Q staging), [16896..21503] sP(128x36),
//              [21504..38399] sO(128x132)
struct PassState { float l0, l1; };

__device__ __forceinline__ PassState attn_pass(
    const float* Kb, const float* Vb, size_t vRS, int nt,
    float* fs, const unsigned (&qa)[16][4], float (&o)[16][4],
    int tid, int g, int t, int qrow) {
    const float SCALE = 0.08838834764831845f;  // 1/sqrt(128)
    float* sP = fs + 16896;
    float m0 = -1e30f, m1 = -1e30f, l0 = 0.f, l1 = 0.f;

    auto issue = [&](int kt, int buf) {
        float* sK = fs + buf * 8448;
        float* sV = sK + 4224;
#pragma unroll
        for (int i = 0; i < 4; i++) {
            int f = tid + i * 256;
            int j = f >> 5, c4 = f & 31;
            cp16(sK + j * 132 + c4 * 4, Kb + (size_t)(kt * 32 + j) * HD + c4 * 4);
            cp16(sV + j * 132 + c4 * 4, Vb + (size_t)(kt * 32 + j) * vRS + c4 * 4);
        }
        CP_COMMIT();
    };

    issue(0, 0);
    for (int kt = 0; kt < nt; kt++) {
        int buf = kt & 1;
        if (kt + 1 < nt) { issue(kt + 1, buf ^ 1); CP_WAIT1(); }
        else             { CP_WAIT0(); }
        __syncthreads();
        float* sK = fs + buf * 8448;
        float* sV = sK + 4224;

        // S = Q @ K^T
        float s[4][4];
#pragma unroll
        for (int nf = 0; nf < 4; nf++)
#pragma unroll
            for (int i = 0; i < 4; i++) s[nf][i] = 0.f;
#pragma unroll
        for (int ks = 0; ks < 16; ks++) {
            int kk = ks * 8;
            unsigned b[4][2];
#pragma unroll
            for (int nf = 0; nf < 4; nf++) {
                int cb = nf * 8 + g;
                b[nf][0] = __float_as_uint(sK[cb * 132 + kk + t]);
                b[nf][1] = __float_as_uint(sK[cb * 132 + kk + t + 4]);
            }
#pragma unroll
            for (int nf = 0; nf < 4; nf++) mma8(s[nf], qa[ks], b[nf]);
        }
#pragma unroll
        for (int nf = 0; nf < 4; nf++)
#pragma unroll
            for (int i = 0; i < 4; i++) s[nf][i] *= SCALE;

        // online softmax
        float mx0 = m0, mx1 = m1;
#pragma unroll
        for (int nf = 0; nf < 4; nf++) {
            mx0 = fmaxf(mx0, fmaxf(s[nf][0], s[nf][1]));
            mx1 = fmaxf(mx1, fmaxf(s[nf][2], s[nf][3]));
        }
        mx0 = fmaxf(mx0, __shfl_xor_sync(0xffffffffu, mx0, 1));
        mx0 = fmaxf(mx0, __shfl_xor_sync(0xffffffffu, mx0, 2));
        mx1 = fmaxf(mx1, __shfl_xor_sync(0xffffffffu, mx1, 1));
        mx1 = fmaxf(mx1, __shfl_xor_sync(0xffffffffu, mx1, 2));
        float corr0 = __expf(m0 - mx0), corr1 = __expf(m1 - mx1);
        m0 = mx0; m1 = mx1;
        l0 *= corr0; l1 *= corr1;
#pragma unroll
        for (int nf = 0; nf < 16; nf++) {
            o[nf][0] *= corr0; o[nf][1] *= corr0;
            o[nf][2] *= corr1; o[nf][3] *= corr1;
        }
        float a0 = 0.f, a1 = 0.f;
#pragma unroll
        for (int nf = 0; nf < 4; nf++) {
            float p0 = tf32r(__expf(s[nf][0] - m0));
            float p1 = tf32r(__expf(s[nf][1] - m0));
            float p2 = tf32r(__expf(s[nf][2] - m1));
            float p3 = tf32r(__expf(s[nf][3] - m1));
            a0 += p0 + p1; a1 += p2 + p3;
            *(float2*)(sP + qrow * 36 + nf * 8 + 2 * t) = make_float2(p0, p1);
            *(float2*)(sP + (qrow + 8) * 36 + nf * 8 + 2 * t) = make_float2(p2, p3);
        }
        a0 += __shfl_xor_sync(0xffffffffu, a0, 1);
        a0 += __shfl_xor_sync(0xffffffffu, a0, 2);
        a1 += __shfl_xor_sync(0xffffffffu, a1, 1);
        a1 += __shfl_xor_sync(0xffffffffu, a1, 2);
        l0 += a0; l1 += a1;
        __syncwarp();

        // O += P @ V
#pragma unroll
        for (int ks2 = 0; ks2 < 4; ks2++) {
            int kk = ks2 * 8;
            unsigned pa[4];
            pa[0] = __float_as_uint(sP[qrow * 36 + kk + t]);
            pa[1] = __float_as_uint(sP[(qrow + 8) * 36 + kk + t]);
            pa[2] = __float_as_uint(sP[qrow * 36 + kk + t + 4]);
            pa[3] = __float_as_uint(sP[(qrow + 8) * 36 + kk + t + 4]);
#pragma unroll
            for (int nf = 0; nf < 16; nf++) {
                unsigned b2[2];
                int cb = nf * 8 + g;
                b2[0] = __float_as_uint(sV[(kk + t) * 132 + cb]);
                b2[1] = __float_as_uint(sV[(kk + t + 4) * 132 + cb]);
                mma8(o[nf], pa, b2);
            }
        }
        __syncthreads();
    }
    return {l0, l1};
}

// grid (24, 18), block 256 (8 warps x 16 q-rows = 128 rows)
__global__ void __launch_bounds__(256, 1) flash_fused() {
    extern __shared__ float fs[];
    float* sO = fs + 21504;  // 128 x 132

    int h = blockIdx.x, qt = blockIdx.y;
    int tid = threadIdx.x, lane = tid & 31, w = tid >> 5;
    int g = lane >> 2, t = lane & 3;
    int qrow = w * 16 + g;

    // stage Q tile (128 x 128) through fs[0..16895]
    const float* Qg = g_q + ((size_t)h * LTOT + qt * 128) * HD;
#pragma unroll
    for (int i = 0; i < 16; i++) {
        int f = tid + i * 256;
        int r = f >> 5, c4 = f & 31;
        cp16(fs + r * 132 + c4 * 4, Qg + (size_t)r * HD + c4 * 4);
    }
    CP_COMMIT(); CP_WAIT0();
    __syncthreads();
    unsigned qa[16][4];
#pragma unroll
    for (int ks = 0; ks < 16; ks++) {
        qa[ks][0] = __float_as_uint(fs[qrow * 132 + ks * 8 + t]);
        qa[ks][1] = __float_as_uint(fs[(qrow + 8) * 132 + ks * 8 + t]);
        qa[ks][2] = __float_as_uint(fs[qrow * 132 + ks * 8 + t + 4]);
        qa[ks][3] = __float_as_uint(fs[(qrow + 8) * 132 + ks * 8 + t + 4]);
    }
    __syncthreads();

    float o[16][4];
#pragma unroll
    for (int nf = 0; nf < 16; nf++)
#pragma unroll
        for (int i = 0; i < 4; i++) o[nf][i] = 0.f;

    // pass 1: main KV (2304 keys)
    PassState p1 = attn_pass(g_k + (size_t)h * LTOT * HD, g_v + (size_t)h * LTOT * HD,
                             HD, LTOT / 32, fs, qa, o, tid, g, t, qrow);
    float i0 = 1.f / p1.l0, i1 = 1.f / p1.l1;
#pragma unroll
    for (int nf = 0; nf < 16; nf++) {
        int cc = nf * 8 + 2 * t;
        *(float2*)(sO + qrow * 132 + cc) = make_float2(o[nf][0] * i0, o[nf][1] * i0);
        *(float2*)(sO + (qrow + 8) * 132 + cc) = make_float2(o[nf][2] * i1, o[nf][3] * i1);
        o[nf][0] = 0.f; o[nf][1] = 0.f; o[nf][2] = 0.f; o[nf][3] = 0.f;
    }

    // pass 2: ref KV (512 keys)
    PassState p2 = attn_pass(g_rk + (size_t)h * REFN * HD, g_rvraw + (size_t)h * HD,
                             HIDN, REFN / 32, fs, qa, o, tid, g, t, qrow);
    float j0 = 1.f / p2.l0, j1 = 1.f / p2.l1;

    // epilogue: sum both passes, write tf32-rounded (g_cat is a GEMM operand)
    float* Ob  = g_cat + (size_t)(qt * 128 + qrow) * CATN + h * HD;
    float* Ob8 = Ob + (size_t)8 * CATN;
#pragma unroll
    for (int nf = 0; nf < 16; nf++) {
        int cc = nf * 8 + 2 * t;
        float2 b0 = *(float2*)(sO + qrow * 132 + cc);
        float2 b1 = *(float2*)(sO + (qrow + 8) * 132 + cc);
        *(float2*)(Ob + cc) = make_float2(tf32r(o[nf][0] * j0 + b0.x),
                                          tf32r(o[nf][1] * j0 + b0.y));
        *(float2*)(Ob8 + cc) = make_float2(tf32r(o[nf][2] * j1 + b1.x),
                                           tf32r(o[nf][3] * j1 + b1.y));
    }
}

// ---------------- launch ----------------
extern "C" void kernel_launch(void* const* d_in, const int* in_sizes, int n_in,
                              void* d_out, int out_size) {
    const float* x          = (const float*)d_in[0];
    const float* vec        = (const float*)d_in[1];
    const float* cosp       = (const float*)d_in[2];
    const float* sinp       = (const float*)d_in[3];
    const float* ref_latent = (const float*)d_in[4];
    const float* ref_cos    = (const float*)d_in[5];
    const float* ref_sin    = (const float*)d_in[6];
    const float* w_mod      = (const float*)d_in[7];
    const float* b_mod      = (const float*)d_in[8];
    const float* w1         = (const float*)d_in[9];
    const float* b1         = (const float*)d_in[10];
    const float* w2         = (const float*)d_in[11];
    const float* b2         = (const float*)d_in[12];
    const float* qn_w       = (const float*)d_in[13];
    const float* kn_w       = (const float*)d_in[14];
    const float* wk_ip      = (const float*)d_in[15];
    const float* bk_ip      = (const float*)d_in[16];
    const float* wv_ip      = (const float*)d_in[17];
    const float* bv_ip      = (const float*)d_in[18];
    const float* ref_kn_w   = (const float*)d_in[19];
    float* out = (float*)d_out;

    const int DSMEM_G0 = 3 * (128 * 36 + 32 * 264) * 4;  // 156672
    const int DSMEM_G3 = 3 * (128 * 36 + 32 * 104) * 4;  // 95232
    const int DSMEM_F  = 38400 * 4;                      // 153600

    static cudaStream_t s2 = nullptr;
    static cudaEvent_t evStart, evW1, evRef, evW2;
    static bool init_done = false;
    if (!init_done) {
        cudaFuncSetAttribute(gemm_lin1, cudaFuncAttributeMaxDynamicSharedMemorySize, DSMEM_G0);
        cudaFuncSetAttribute(gemm_out, cudaFuncAttributeMaxDynamicSharedMemorySize, DSMEM_G3);
        cudaFuncSetAttribute(flash_fused, cudaFuncAttributeMaxDynamicSharedMemorySize, DSMEM_F);
        cudaStreamCreateWithFlags(&s2, cudaStreamNonBlocking);
        cudaEventCreateWithFlags(&evStart, cudaEventDisableTiming);
        cudaEventCreateWithFlags(&evW1, cudaEventDisableTiming);
        cudaEventCreateWithFlags(&evRef, cudaEventDisableTiming);
        cudaEventCreateWithFlags(&evW2, cudaEventDisableTiming);
        init_done = true;
    }

    float* w1r; cudaGetSymbolAddress((void**)&w1r, g_w1r);
    float* w2r; cudaGetSymbolAddress((void**)&w2r, g_w2r);

    // fork side stream: w1 pre-round first (gemm_lin1 gate), then ref-KV path, then w2
    cudaEventRecord(evStart, 0);
    cudaStreamWaitEvent(s2, evStart, 0);
    round_w<<<1184, 256, 0, s2>>>(w1, w1r, (size_t)HIDN * NN1 / 4);
    cudaEventRecord(evW1, s2);
    gemm_tf32<1><<<dim3(4, 24), 256, 0, s2>>>(ref_latent, wk_ip, bk_ip, REFN, HIDN, HIDN);
    gemm_tf32<2><<<dim3(4, 24), 256, 0, s2>>>(ref_latent, wv_ip, bv_ip, REFN, HIDN, HIDN);
    refprep<<<dim3(24, REFN), 128, 0, s2>>>(ref_kn_w, ref_cos, ref_sin);
    cudaEventRecord(evRef, s2);
    round_w<<<1184, 256, 0, s2>>>(w2, w2r, (size_t)CATN * HIDN / 4);
    cudaEventRecord(evW2, s2);

    // main stream: mod chain + layernorm overlap the w1 pre-round
    mod_gemv<<<dim3(36, 8), 256>>>(vec, w_mod);
    mod_reduce<<<36, 256>>>(b_mod);
    ln_mod_kernel<<<LTOT, 256>>>(x);
    cudaStreamWaitEvent(0, evW1, 0);
    gemm_lin1<<<dim3(18, 84), 256, DSMEM_G0>>>(b1, LTOT, NN1, HIDN);
    qkvprep<<<dim3(24, LTOT), 128>>>(qn_w, kn_w, cosp, sinp);
    cudaStreamWaitEvent(0, evRef, 0);
    flash_fused<<<dim3(24, 18), 256, DSMEM_F>>>();
    cudaStreamWaitEvent(0, evW2, 0);
    gemm_out<<<dim3(18, 32), 256, DSMEM_G3>>>(b2, out, x, LTOT, HIDN, CATN);
}

// round 17
// speedup vs baseline: 1.5560x; 1.5560x over previous
#include <cuda_runtime.h>
#include <cuda_bf16.h>
#include <cstdint>
#include <cstddef>

#define HIDN  3072
#define LTOT  2304
#define IMGN  2048
#define NHEAD 24
#define HD    128
#define REFN  512
#define QKV3  9216
#define NN1   21504
#define CATN  15360

// ---------------- scratch (device globals; no allocation) ----------------
static __device__ float g_modp[8 * QKV3];
static __device__ float g_mod[QKV3];                          // shift | scl | gate
static __device__ float g_xmod[(size_t)LTOT * HIDN];          // tf32-rounded
static __device__ float g_qkv[(size_t)LTOT * QKV3];
static __device__ float g_q[(size_t)NHEAD * LTOT * HD];       // tf32-rounded
static __device__ float g_k[(size_t)NHEAD * LTOT * HD];       // tf32-rounded
static __device__ float g_v[(size_t)NHEAD * LTOT * HD];       // tf32-rounded
static __device__ float g_rkraw[(size_t)REFN * HIDN];
static __device__ float g_rvraw[(size_t)REFN * HIDN];         // tf32-rounded
static __device__ float g_rk[(size_t)NHEAD * REFN * HD];      // tf32-rounded
static __device__ float g_cat[(size_t)LTOT * CATN];           // tf32-rounded [attn | gelu(mlp)]
static __device__ float g_w1r[(size_t)HIDN * NN1];            // tf32-rounded w1
static __device__ float g_w2r[(size_t)CATN * HIDN];           // tf32-rounded w2

// ---------------- helpers ----------------
__device__ __forceinline__ float tf32r(float x) {
    unsigned u;
    asm("cvt.rna.tf32.f32 %0, %1;" : "=r"(u) : "f"(x));
    return __uint_as_float(u);
}

__device__ __forceinline__ void mma8(float c[4], const unsigned a[4], const unsigned b[2]) {
    asm volatile(
        "mma.sync.aligned.m16n8k8.row.col.f32.tf32.tf32.f32 "
        "{%0,%1,%2,%3}, {%4,%5,%6,%7}, {%8,%9}, {%0,%1,%2,%3};\n"
        : "+f"(c[0]), "+f"(c[1]), "+f"(c[2]), "+f"(c[3])
        : "r"(a[0]), "r"(a[1]), "r"(a[2]), "r"(a[3]), "r"(b[0]), "r"(b[1]));
}

__device__ __forceinline__ void cp16(const float* smem_dst, const float* gsrc) {
    unsigned s = (unsigned)__cvta_generic_to_shared(smem_dst);
    asm volatile("cp.async.cg.shared.global [%0], [%1], 16;" :: "r"(s), "l"(gsrc));
}
#define CP_COMMIT() asm volatile("cp.async.commit_group;")
#define CP_WAIT0()  asm volatile("cp.async.wait_group 0;")
#define CP_WAIT1()  asm volatile("cp.async.wait_group 1;")

__device__ __forceinline__ float gelu_t(float v) {
    return 0.5f * v * (1.0f + tanhf(0.7978845608028654f * (v + 0.044715f * v * v * v)));
}

// ---------------- weight pre-round to tf32 ----------------
__global__ void round_w(const float* __restrict__ src, float* __restrict__ dst, size_t n4) {
    size_t stride = (size_t)gridDim.x * blockDim.x;
    for (size_t i = blockIdx.x * (size_t)blockDim.x + threadIdx.x; i < n4; i += stride) {
        float4 v = *(const float4*)(src + i * 4);
        v.x = tf32r(v.x); v.y = tf32r(v.y); v.z = tf32r(v.z); v.w = tf32r(v.w);
        *(float4*)(dst + i * 4) = v;
    }
}

// ---------------- mod = silu(vec) @ w_mod + b_mod (split-K) ----------------
__global__ void mod_gemv(const float* __restrict__ vec, const float* __restrict__ w) {
    __shared__ float sv2[384];
    int ky = blockIdx.y;
    int k0 = ky * 384;
    for (int i = threadIdx.x; i < 384; i += 256) {
        float xx = vec[k0 + i];
        sv2[i] = xx / (1.f + __expf(-xx));
    }
    __syncthreads();
    int c = blockIdx.x * 256 + threadIdx.x;
    const float* wp = w + (size_t)k0 * QKV3 + c;
    float acc = 0.f;
#pragma unroll 8
    for (int k = 0; k < 384; ++k) acc += sv2[k] * wp[(size_t)k * QKV3];
    g_modp[ky * QKV3 + c] = acc;
}

__global__ void mod_reduce(const float* __restrict__ bmod) {
    int c = blockIdx.x * 256 + threadIdx.x;
    float a = bmod[c];
#pragma unroll
    for (int ky = 0; ky < 8; ky++) a += g_modp[ky * QKV3 + c];
    g_mod[c] = a;
}

// ---------------- x_mod = layernorm(x)*(1+scl)+shift  (tf32-rounded) ----------------
__global__ void ln_mod_kernel(const float* __restrict__ x) {
    __shared__ float sh[16];
    int row = blockIdx.x;
    const float* xp = x + (size_t)row * HIDN;
    float4 v[3];
    float s = 0.f, q = 0.f;
#pragma unroll
    for (int i = 0; i < 3; i++) {
        v[i] = *(const float4*)(xp + (threadIdx.x + i * 256) * 4);
        s += v[i].x + v[i].y + v[i].z + v[i].w;
        q += v[i].x * v[i].x + v[i].y * v[i].y + v[i].z * v[i].z + v[i].w * v[i].w;
    }
#pragma unroll
    for (int o = 16; o; o >>= 1) {
        s += __shfl_xor_sync(0xffffffffu, s, o);
        q += __shfl_xor_sync(0xffffffffu, q, o);
    }
    int wid = threadIdx.x >> 5;
    if ((threadIdx.x & 31) == 0) { sh[wid] = s; sh[8 + wid] = q; }
    __syncthreads();
    if (threadIdx.x == 0) {
        float a = 0.f, b = 0.f;
#pragma unroll
        for (int i = 0; i < 8; i++) { a += sh[i]; b += sh[8 + i]; }
        sh[0] = a; sh[8] = b;
    }
    __syncthreads();
    float mean = sh[0] * (1.f / HIDN);
    float var  = sh[8] * (1.f / HIDN) - mean * mean;
    float inv  = rsqrtf(var + 1e-6f);
#pragma unroll
    for (int i = 0; i < 3; i++) {
        int c = (threadIdx.x + i * 256) * 4;
        float4 o;
        o.x = tf32r((v[i].x - mean) * inv * (1.f + g_mod[HIDN + c + 0]) + g_mod[c + 0]);
        o.y = tf32r((v[i].y - mean) * inv * (1.f + g_mod[HIDN + c + 1]) + g_mod[c + 1]);
        o.z = tf32r((v[i].z - mean) * inv * (1.f + g_mod[HIDN + c + 2]) + g_mod[c + 2]);
        o.w = tf32r((v[i].w - mean) * inv * (1.f + g_mod[HIDN + c + 3]) + g_mod[c + 3]);
        *(float4*)(g_xmod + (size_t)row * HIDN + c) = o;
    }
}

// ---------------- lin1 GEMM: 128x256 tile, warp tile 64x64, 3-stage, 1 sync/tile ----------------
__global__ void __launch_bounds__(256, 1) gemm_lin1(
    const float* __restrict__ bias, int M, int N, int K) {
    extern __shared__ float ds[];
    const int BUF = 13056;  // 128*36 + 32*264 floats per stage
    const float* A = g_xmod;
    const float* B = g_w1r;

    int tid = threadIdx.x, lane = tid & 31, wid = tid >> 5;
    int g = lane >> 2, t = lane & 3;
    int wm = wid >> 2, wn = wid & 3;
    int bm = blockIdx.x * 128, bn = blockIdx.y * 256;

    float c[4][8][4];
#pragma unroll
    for (int mf = 0; mf < 4; mf++)
#pragma unroll
        for (int nf = 0; nf < 8; nf++)
#pragma unroll
            for (int i = 0; i < 4; i++) c[mf][nf][i] = 0.f;

    const float* Ap = A + (size_t)bm * K;
    const float* Bp = B + bn;

    auto issue = [&](int kt, int buf) {
        int k0 = kt << 5;
        float* sA = ds + buf * BUF;
        float* sB = sA + 4608;
#pragma unroll
        for (int i = 0; i < 4; i++) {
            int f = tid + i * 256;
            int r = f >> 3, cc = f & 7;
            cp16(sA + r * 36 + cc * 4, Ap + (size_t)r * K + k0 + cc * 4);
        }
#pragma unroll
        for (int i = 0; i < 8; i++) {
            int f = tid + i * 256;
            int r = f >> 6, cc = f & 63;
            cp16(sB + r * 264 + cc * 4, Bp + (size_t)(k0 + r) * N + cc * 4);
        }
        CP_COMMIT();
    };

    int nt = K >> 5;  // 96
    issue(0, 0); issue(1, 1);
    for (int it = 0; it < nt; it++) {
        if (it == nt - 1) CP_WAIT0(); else CP_WAIT1();
        __syncthreads();
        if (it + 2 < nt) issue(it + 2, (it + 2) % 3);
        float* sA = ds + (it % 3) * BUF;
        float* sB = sA + 4608;
#pragma unroll
        for (int ks = 0; ks < 4; ks++) {
            int kk = ks * 8;
            unsigned a[4][4], b[8][2];
#pragma unroll
            for (int mf = 0; mf < 4; mf++) {
                int rb = wm * 64 + mf * 16 + g;
                a[mf][0] = __float_as_uint(sA[rb * 36 + kk + t]);
                a[mf][1] = __float_as_uint(sA[(rb + 8) * 36 + kk + t]);
                a[mf][2] = __float_as_uint(sA[rb * 36 + kk + t + 4]);
                a[mf][3] = __float_as_uint(sA[(rb + 8) * 36 + kk + t + 4]);
            }
#pragma unroll
            for (int nf = 0; nf < 8; nf++) {
                int cb = wn * 64 + nf * 8 + g;
                b[nf][0] = __float_as_uint(sB[(kk + t) * 264 + cb]);
                b[nf][1] = __float_as_uint(sB[(kk + t + 4) * 264 + cb]);
            }
#pragma unroll
            for (int mf = 0; mf < 4; mf++)
#pragma unroll
                for (int nf = 0; nf < 8; nf++) mma8(c[mf][nf], a[mf], b[nf]);
        }
    }

#pragma unroll
    for (int mf = 0; mf < 4; mf++)
#pragma unroll
        for (int nf = 0; nf < 8; nf++) {
            int row = bm + wm * 64 + mf * 16 + g;
            int col = bn + wn * 64 + nf * 8 + 2 * t;
            float2 b2 = *(const float2*)(bias + col);
            float2 v0 = make_float2(c[mf][nf][0] + b2.x, c[mf][nf][1] + b2.y);
            float2 v1 = make_float2(c[mf][nf][2] + b2.x, c[mf][nf][3] + b2.y);
            if (col < QKV3) {
                *(float2*)(g_qkv + (size_t)row * QKV3 + col) = v0;
                *(float2*)(g_qkv + (size_t)(row + 8) * QKV3 + col) = v1;
            } else {
                int cc = HIDN + (col - QKV3);
                *(float2*)(g_cat + (size_t)row * CATN + cc) =
                    make_float2(tf32r(gelu_t(v0.x)), tf32r(gelu_t(v0.y)));
                *(float2*)(g_cat + (size_t)(row + 8) * CATN + cc) =
                    make_float2(tf32r(gelu_t(v1.x)), tf32r(gelu_t(v1.y)));
            }
        }
}

// ---------------- out GEMM: 128x128 tile, 3-stage, 1 sync/tile, 2 CTAs/SM (R15 proven) ----------------
__global__ void __launch_bounds__(256, 2) gemm_out(
    const float* __restrict__ bias, float* __restrict__ O,
    const float* __restrict__ resid, int M, int N, int K) {
    extern __shared__ float ds[];
    const int BUF = 8960;
    const float* A = g_cat;
    const float* B = g_w2r;

    int tid = threadIdx.x, lane = tid & 31, wid = tid >> 5;
    int g = lane >> 2, t = lane & 3;
    int wm = wid >> 1, wn = wid & 1;
    int bm = blockIdx.x * 128, bn = blockIdx.y * 128;

    float c[2][8][4];
#pragma unroll
    for (int mf = 0; mf < 2; mf++)
#pragma unroll
        for (int nf = 0; nf < 8; nf++)
#pragma unroll
            for (int i = 0; i < 4; i++) c[mf][nf][i] = 0.f;

    const float* Ap = A + (size_t)bm * K;
    const float* Bp = B + bn;

    auto issue = [&](int kt, int buf) {
        int k0 = kt << 5;
        float* sA = ds + buf * BUF;
        float* sB = sA + 4608;
#pragma unroll
        for (int i = 0; i < 4; i++) {
            int f = tid + i * 256;
            int r = f >> 3, cc = f & 7;
            cp16(sA + r * 36 + cc * 4, Ap + (size_t)r * K + k0 + cc * 4);
        }
#pragma unroll
        for (int i = 0; i < 4; i++) {
            int f = tid + i * 256;
            int r = f >> 5, cc = f & 31;
            cp16(sB + r * 136 + cc * 4, Bp + (size_t)(k0 + r) * N + cc * 4);
        }
        CP_COMMIT();
    };

    int nt = K >> 5;  // 480
    issue(0, 0); issue(1, 1);
    for (int it = 0; it < nt; it++) {
        if (it == nt - 1) CP_WAIT0(); else CP_WAIT1();
        __syncthreads();
        if (it + 2 < nt) issue(it + 2, (it + 2) % 3);
        float* sA = ds + (it % 3) * BUF;
        float* sB = sA + 4608;
#pragma unroll
        for (int ks = 0; ks < 4; ks++) {
            int kk = ks * 8;
            unsigned a[2][4], b[8][2];
#pragma unroll
            for (int mf = 0; mf < 2; mf++) {
                int rb = wm * 32 + mf * 16 + g;
                a[mf][0] = __float_as_uint(sA[rb * 36 + kk + t]);
                a[mf][1] = __float_as_uint(sA[(rb + 8) * 36 + kk + t]);
                a[mf][2] = __float_as_uint(sA[rb * 36 + kk + t + 4]);
                a[mf][3] = __float_as_uint(sA[(rb + 8) * 36 + kk + t + 4]);
            }
#pragma unroll
            for (int nf = 0; nf < 8; nf++) {
                int cb = wn * 64 + nf * 8 + g;
                b[nf][0] = __float_as_uint(sB[(kk + t) * 136 + cb]);
                b[nf][1] = __float_as_uint(sB[(kk + t + 4) * 136 + cb]);
            }
#pragma unroll
            for (int mf = 0; mf < 2; mf++)
#pragma unroll
                for (int nf = 0; nf < 8; nf++) mma8(c[mf][nf], a[mf], b[nf]);
        }
    }

#pragma unroll
    for (int mf = 0; mf < 2; mf++)
#pragma unroll
        for (int nf = 0; nf < 8; nf++) {
            int row = bm + wm * 32 + mf * 16 + g;
            int col = bn + wn * 64 + nf * 8 + 2 * t;
            float2 b2 = *(const float2*)(bias + col);
            float2 v0 = make_float2(c[mf][nf][0] + b2.x, c[mf][nf][1] + b2.y);
            float2 v1 = make_float2(c[mf][nf][2] + b2.x, c[mf][nf][3] + b2.y);
            float2 gt = *(const float2*)(g_mod + 2 * HIDN + col);
            size_t i0 = (size_t)row * HIDN + col;
            size_t i1 = (size_t)(row + 8) * HIDN + col;
            float2 r0 = *(const float2*)(resid + i0);
            float2 r1 = *(const float2*)(resid + i1);
            *(float2*)(O + i0) = make_float2(r0.x + gt.x * v0.x, r0.y + gt.y * v0.y);
            *(float2*)(O + i1) = make_float2(r1.x + gt.x * v1.x, r1.y + gt.y * v1.y);
        }
}

// ---------------- register-path TF32 GEMM (EPI 1 = ref_k, 2 = ref_v) ----------------
template <int EPI>
__global__ void __launch_bounds__(256) gemm_tf32(
    const float* __restrict__ Aarg, const float* __restrict__ B,
    const float* __restrict__ bias, int M, int N, int K) {
    __shared__ float sA[128 * 36];
    __shared__ float sB[32 * 136];
    const float* A = Aarg;

    int tid = threadIdx.x, lane = tid & 31, wid = tid >> 5;
    int g = lane >> 2, t = lane & 3;
    int wm = wid >> 1, wn = wid & 1;
    int bm = blockIdx.x * 128, bn = blockIdx.y * 128;

    float c[2][8][4];
#pragma unroll
    for (int mf = 0; mf < 2; mf++)
#pragma unroll
        for (int nf = 0; nf < 8; nf++)
#pragma unroll
            for (int i = 0; i < 4; i++) c[mf][nf][i] = 0.f;

    const float* Ap = A + (size_t)bm * K;
    const float* Bp = B + bn;

    for (int k0 = 0; k0 < K; k0 += 32) {
        __syncthreads();
#pragma unroll
        for (int i = 0; i < 4; i++) {
            int f = tid + i * 256;
            int r = f >> 3, cc = f & 7;
            float4 v = *(const float4*)(Ap + (size_t)r * K + k0 + cc * 4);
            float* d = sA + r * 36 + cc * 4;
            d[0] = tf32r(v.x); d[1] = tf32r(v.y); d[2] = tf32r(v.z); d[3] = tf32r(v.w);
        }
#pragma unroll
        for (int i = 0; i < 4; i++) {
            int f = tid + i * 256;
            int r = f >> 5, cc = f & 31;
            float4 v = *(const float4*)(Bp + (size_t)(k0 + r) * N + cc * 4);
            float* d = sB + r * 136 + cc * 4;
            d[0] = tf32r(v.x); d[1] = tf32r(v.y); d[2] = tf32r(v.z); d[3] = tf32r(v.w);
        }
        __syncthreads();
#pragma unroll
        for (int ks = 0; ks < 4; ks++) {
            int kk = ks * 8;
            unsigned a[2][4], b[8][2];
#pragma unroll
            for (int mf = 0; mf < 2; mf++) {
                int rb = wm * 32 + mf * 16 + g;
                a[mf][0] = __float_as_uint(sA[rb * 36 + kk + t]);
                a[mf][1] = __float_as_uint(sA[(rb + 8) * 36 + kk + t]);
                a[mf][2] = __float_as_uint(sA[rb * 36 + kk + t + 4]);
                a[mf][3] = __float_as_uint(sA[(rb + 8) * 36 + kk + t + 4]);
            }
#pragma unroll
            for (int nf = 0; nf < 8; nf++) {
                int cb = wn * 64 + nf * 8 + g;
                b[nf][0] = __float_as_uint(sB[(kk + t) * 136 + cb]);
                b[nf][1] = __float_as_uint(sB[(kk + t + 4) * 136 + cb]);
            }
#pragma unroll
            for (int mf = 0; mf < 2; mf++)
#pragma unroll
                for (int nf = 0; nf < 8; nf++) mma8(c[mf][nf], a[mf], b[nf]);
        }
    }

#pragma unroll
    for (int mf = 0; mf < 2; mf++)
#pragma unroll
        for (int nf = 0; nf < 8; nf++)
#pragma unroll
            for (int i = 0; i < 4; i++) {
                int row = bm + wm * 32 + mf * 16 + g + ((i >> 1) ? 8 : 0);
                int col = bn + wn * 64 + nf * 8 + t * 2 + (i & 1);
                float v = c[mf][nf][i] + bias[col];
                if (EPI == 1) g_rkraw[(size_t)row * HIDN + col] = v;
                else          g_rvraw[(size_t)row * HIDN + col] = tf32r(v);
            }
}

// ---------------- qkv prep: rmsnorm + rope + relayout (tf32-rounded) ----------------
__global__ void qkvprep(const float* __restrict__ qn_w, const float* __restrict__ kn_w,
                        const float* __restrict__ cosp, const float* __restrict__ sinp) {
    int h = blockIdx.x, row = blockIdx.y, t = threadIdx.x;
    const float* base = g_qkv + (size_t)row * QKV3 + h * HD;
    float q = base[t], k = base[HIDN + t], v = base[2 * HIDN + t];
    __shared__ float red[8];
    float sq = q * q, sk = k * k;
#pragma unroll
    for (int o = 16; o; o >>= 1) {
        sq += __shfl_xor_sync(0xffffffffu, sq, o);
        sk += __shfl_xor_sync(0xffffffffu, sk, o);
    }
    int w = t >> 5;
    if ((t & 31) == 0) { red[w] = sq; red[4 + w] = sk; }
    __syncthreads();
    float ssq = red[0] + red[1] + red[2] + red[3];
    float ssk = red[4] + red[5] + red[6] + red[7];
    q *= rsqrtf(ssq * (1.f / HD) + 1e-6f) * qn_w[t];
    k *= rsqrtf(ssk * (1.f / HD) + 1e-6f) * kn_w[t];
    if (row < IMGN) {
        float cv = cosp[row * 64 + (t >> 1)], sv = sinp[row * 64 + (t >> 1)];
        float qo = __shfl_xor_sync(0xffffffffu, q, 1);
        float ko = __shfl_xor_sync(0xffffffffu, k, 1);
        if ((t & 1) == 0) { q = q * cv - qo * sv; k = k * cv - ko * sv; }
        else              { q = qo * sv + q * cv; k = ko * sv + k * cv; }
    }
    size_t oidx = ((size_t)h * LTOT + row) * HD + t;
    g_q[oidx] = tf32r(q); g_k[oidx] = tf32r(k); g_v[oidx] = tf32r(v);
}

// ---------------- ref_k prep: rmsnorm + rope (tf32-rounded) ----------------
__global__ void refprep(const float* __restrict__ ref_kn_w,
                        const float* __restrict__ rcos, const float* __restrict__ rsin) {
    int h = blockIdx.x, row = blockIdx.y, t = threadIdx.x;
    float k = g_rkraw[(size_t)row * HIDN + h * HD + t];
    __shared__ float red[4];
    float sk = k * k;
#pragma unroll
    for (int o = 16; o; o >>= 1) sk += __shfl_xor_sync(0xffffffffu, sk, o);
    int w = t >> 5;
    if ((t & 31) == 0) red[w] = sk;
    __syncthreads();
    float ssk = red[0] + red[1] + red[2] + red[3];
    k *= rsqrtf(ssk * (1.f / HD) + 1e-6f) * ref_kn_w[t];
    float cv = rcos[row * 64 + (t >> 1)], sv = rsin[row * 64 + (t >> 1)];
    float ko = __shfl_xor_sync(0xffffffffu, k, 1);
    if ((t & 1) == 0) k = k * cv - ko * sv;
    else              k = ko * sv + k * cv;
    g_rk[((size_t)h * REFN + row) * HD + t] = tf32r(k);
}

// ---------------- fused flash attention: 128-row q tiles, 8 warps ----------------
// smem floats: [0..16895] 2-stage K|V (also Q staging), [16896..21503] sP(128x36),
//              [21504..38399] sO(128x132)
struct PassState { float l0, l1; };

__device__ __forceinline__ PassState attn_pass(
    const float* Kb, const float* Vb, size_t vRS, int nt,
    float* fs, const unsigned (&qa)[16][4], float (&o)[16][4],
    int tid, int g, int t, int qrow) {
    const float SCALE = 0.08838834764831845f;  // 1/sqrt(128)
    float* sP = fs + 16896;
    float m0 = -1e30f, m1 = -1e30f, l0 = 0.f, l1 = 0.f;

    auto issue = [&](int kt, int buf) {
        float* sK = fs + buf * 8448;
        float* sV = sK + 4224;
#pragma unroll
        for (int i = 0; i < 4; i++) {
            int f = tid + i * 256;
            int j = f >> 5, c4 = f & 31;
            cp16(sK + j * 132 + c4 * 4, Kb + (size_t)(kt * 32 + j) * HD + c4 * 4);
            cp16(sV + j * 132 + c4 * 4, Vb + (size_t)(kt * 32 + j) * vRS + c4 * 4);
        }
        CP_COMMIT();
    };

    issue(0, 0);
    for (int kt = 0; kt < nt; kt++) {
        int buf = kt & 1;
        if (kt + 1 < nt) { issue(kt + 1, buf ^ 1); CP_WAIT1(); }
        else             { CP_WAIT0(); }
        __syncthreads();
        float* sK = fs + buf * 8448;
        float* sV = sK + 4224;

        // S = Q @ K^T
        float s[4][4];
#pragma unroll
        for (int nf = 0; nf < 4; nf++)
#pragma unroll
            for (int i = 0; i < 4; i++) s[nf][i] = 0.f;
#pragma unroll
        for (int ks = 0; ks < 16; ks++) {
            int kk = ks * 8;
            unsigned b[4][2];
#pragma unroll
            for (int nf = 0; nf < 4; nf++) {
                int cb = nf * 8 + g;
                b[nf][0] = __float_as_uint(sK[cb * 132 + kk + t]);
                b[nf][1] = __float_as_uint(sK[cb * 132 + kk + t + 4]);
            }
#pragma unroll
            for (int nf = 0; nf < 4; nf++) mma8(s[nf], qa[ks], b[nf]);
        }
#pragma unroll
        for (int nf = 0; nf < 4; nf++)
#pragma unroll
            for (int i = 0; i < 4; i++) s[nf][i] *= SCALE;

        // online softmax
        float mx0 = m0, mx1 = m1;
#pragma unroll
        for (int nf = 0; nf < 4; nf++) {
            mx0 = fmaxf(mx0, fmaxf(s[nf][0], s[nf][1]));
            mx1 = fmaxf(mx1, fmaxf(s[nf][2], s[nf][3]));
        }
        mx0 = fmaxf(mx0, __shfl_xor_sync(0xffffffffu, mx0, 1));
        mx0 = fmaxf(mx0, __shfl_xor_sync(0xffffffffu, mx0, 2));
        mx1 = fmaxf(mx1, __shfl_xor_sync(0xffffffffu, mx1, 1));
        mx1 = fmaxf(mx1, __shfl_xor_sync(0xffffffffu, mx1, 2));
        float corr0 = __expf(m0 - mx0), corr1 = __expf(m1 - mx1);
        m0 = mx0; m1 = mx1;
        l0 *= corr0; l1 *= corr1;
#pragma unroll
        for (int nf = 0; nf < 16; nf++) {
            o[nf][0] *= corr0; o[nf][1] *= corr0;
            o[nf][2] *= corr1; o[nf][3] *= corr1;
        }
        float a0 = 0.f, a1 = 0.f;
#pragma unroll
        for (int nf = 0; nf < 4; nf++) {
            float p0 = tf32r(__expf(s[nf][0] - m0));
            float p1 = tf32r(__expf(s[nf][1] - m0));
            float p2 = tf32r(__expf(s[nf][2] - m1));
            float p3 = tf32r(__expf(s[nf][3] - m1));
            a0 += p0 + p1; a1 += p2 + p3;
            *(float2*)(sP + qrow * 36 + nf * 8 + 2 * t) = make_float2(p0, p1);
            *(float2*)(sP + (qrow + 8) * 36 + nf * 8 + 2 * t) = make_float2(p2, p3);
        }
        a0 += __shfl_xor_sync(0xffffffffu, a0, 1);
        a0 += __shfl_xor_sync(0xffffffffu, a0, 2);
        a1 += __shfl_xor_sync(0xffffffffu, a1, 1);
        a1 += __shfl_xor_sync(0xffffffffu, a1, 2);
        l0 += a0; l1 += a1;
        __syncwarp();

        // O += P @ V
#pragma unroll
        for (int ks2 = 0; ks2 < 4; ks2++) {
            int kk = ks2 * 8;
            unsigned pa[4];
            pa[0] = __float_as_uint(sP[qrow * 36 + kk + t]);
            pa[1] = __float_as_uint(sP[(qrow + 8) * 36 + kk + t]);
            pa[2] = __float_as_uint(sP[qrow * 36 + kk + t + 4]);
            pa[3] = __float_as_uint(sP[(qrow + 8) * 36 + kk + t + 4]);
#pragma unroll
            for (int nf = 0; nf < 16; nf++) {
                unsigned b2[2];
                int cb = nf * 8 + g;
                b2[0] = __float_as_uint(sV[(kk + t) * 132 + cb]);
                b2[1] = __float_as_uint(sV[(kk + t + 4) * 132 + cb]);
                mma8(o[nf], pa, b2);
            }
        }
        __syncthreads();
    }
    return {l0, l1};
}

// grid (24, 18), block 256 (8 warps x 16 q-rows = 128 rows)
__global__ void __launch_bounds__(256, 1) flash_fused() {
    extern __shared__ float fs[];
    float* sO = fs + 21504;  // 128 x 132

    int h = blockIdx.x, qt = blockIdx.y;
    int tid = threadIdx.x, lane = tid & 31, w = tid >> 5;
    int g = lane >> 2, t = lane & 3;
    int qrow = w * 16 + g;

    // stage Q tile (128 x 128) through fs[0..16895]
    const float* Qg = g_q + ((size_t)h * LTOT + qt * 128) * HD;
#pragma unroll
    for (int i = 0; i < 16; i++) {
        int f = tid + i * 256;
        int r = f >> 5, c4 = f & 31;
        cp16(fs + r * 132 + c4 * 4, Qg + (size_t)r * HD + c4 * 4);
    }
    CP_COMMIT(); CP_WAIT0();
    __syncthreads();
    unsigned qa[16][4];
#pragma unroll
    for (int ks = 0; ks < 16; ks++) {
        qa[ks][0] = __float_as_uint(fs[qrow * 132 + ks * 8 + t]);
        qa[ks][1] = __float_as_uint(fs[(qrow + 8) * 132 + ks * 8 + t]);
        qa[ks][2] = __float_as_uint(fs[qrow * 132 + ks * 8 + t + 4]);
        qa[ks][3] = __float_as_uint(fs[(qrow + 8) * 132 + ks * 8 + t + 4]);
    }
    __syncthreads();

    float o[16][4];
#pragma unroll
    for (int nf = 0; nf < 16; nf++)
#pragma unroll
        for (int i = 0; i < 4; i++) o[nf][i] = 0.f;

    // pass 1: main KV (2304 keys)
    PassState p1 = attn_pass(g_k + (size_t)h * LTOT * HD, g_v + (size_t)h * LTOT * HD,
                             HD, LTOT / 32, fs, qa, o, tid, g, t, qrow);
    float i0 = 1.f / p1.l0, i1 = 1.f / p1.l1;
#pragma unroll
    for (int nf = 0; nf < 16; nf++) {
        int cc = nf * 8 + 2 * t;
        *(float2*)(sO + qrow * 132 + cc) = make_float2(o[nf][0] * i0, o[nf][1] * i0);
        *(float2*)(sO + (qrow + 8) * 132 + cc) = make_float2(o[nf][2] * i1, o[nf][3] * i1);
        o[nf][0] = 0.f; o[nf][1] = 0.f; o[nf][2] = 0.f; o[nf][3] = 0.f;
    }

    // pass 2: ref KV (512 keys)
    PassState p2 = attn_pass(g_rk + (size_t)h * REFN * HD, g_rvraw + (size_t)h * HD,
                             HIDN, REFN / 32, fs, qa, o, tid, g, t, qrow);
    float j0 = 1.f / p2.l0, j1 = 1.f / p2.l1;

    // epilogue: sum both passes, write tf32-rounded (g_cat is a GEMM operand)
    float* Ob  = g_cat + (size_t)(qt * 128 + qrow) * CATN + h * HD;
    float* Ob8 = Ob + (size_t)8 * CATN;
#pragma unroll
    for (int nf = 0; nf < 16; nf++) {
        int cc = nf * 8 + 2 * t;
        float2 b0 = *(float2*)(sO + qrow * 132 + cc);
        float2 b1 = *(float2*)(sO + (qrow + 8) * 132 + cc);
        *(float2*)(Ob + cc) = make_float2(tf32r(o[nf][0] * j0 + b0.x),
                                          tf32r(o[nf][1] * j0 + b0.y));
        *(float2*)(Ob8 + cc) = make_float2(tf32r(o[nf][2] * j1 + b1.x),
                                           tf32r(o[nf][3] * j1 + b1.y));
    }
}

// ---------------- launch ----------------
extern "C" void kernel_launch(void* const* d_in, const int* in_sizes, int n_in,
                              void* d_out, int out_size) {
    const float* x          = (const float*)d_in[0];
    const float* vec        = (const float*)d_in[1];
    const float* cosp       = (const float*)d_in[2];
    const float* sinp       = (const float*)d_in[3];
    const float* ref_latent = (const float*)d_in[4];
    const float* ref_cos    = (const float*)d_in[5];
    const float* ref_sin    = (const float*)d_in[6];
    const float* w_mod      = (const float*)d_in[7];
    const float* b_mod      = (const float*)d_in[8];
    const float* w1         = (const float*)d_in[9];
    const float* b1         = (const float*)d_in[10];
    const float* w2         = (const float*)d_in[11];
    const float* b2         = (const float*)d_in[12];
    const float* qn_w       = (const float*)d_in[13];
    const float* kn_w       = (const float*)d_in[14];
    const float* wk_ip      = (const float*)d_in[15];
    const float* bk_ip      = (const float*)d_in[16];
    const float* wv_ip      = (const float*)d_in[17];
    const float* bv_ip      = (const float*)d_in[18];
    const float* ref_kn_w   = (const float*)d_in[19];
    float* out = (float*)d_out;

    const int DSMEM_G0 = 3 * (128 * 36 + 32 * 264) * 4;  // 156672
    const int DSMEM_G3 = 3 * (128 * 36 + 32 * 136) * 4;  // 107520
    const int DSMEM_F  = 38400 * 4;                      // 153600

    static cudaStream_t s2 = nullptr;
    static cudaEvent_t evStart, evW1, evRef, evW2;
    static bool init_done = false;
    if (!init_done) {
        cudaFuncSetAttribute(gemm_lin1, cudaFuncAttributeMaxDynamicSharedMemorySize, DSMEM_G0);
        cudaFuncSetAttribute(gemm_out, cudaFuncAttributeMaxDynamicSharedMemorySize, DSMEM_G3);
        cudaFuncSetAttribute(flash_fused, cudaFuncAttributeMaxDynamicSharedMemorySize, DSMEM_F);
        cudaStreamCreateWithFlags(&s2, cudaStreamNonBlocking);
        cudaEventCreateWithFlags(&evStart, cudaEventDisableTiming);
        cudaEventCreateWithFlags(&evW1, cudaEventDisableTiming);
        cudaEventCreateWithFlags(&evRef, cudaEventDisableTiming);
        cudaEventCreateWithFlags(&evW2, cudaEventDisableTiming);
        init_done = true;
    }

    float* w1r; cudaGetSymbolAddress((void**)&w1r, g_w1r);
    float* w2r; cudaGetSymbolAddress((void**)&w2r, g_w2r);

    // fork side stream: w1 pre-round first (gemm_lin1 gate), then ref-KV path, then w2
    cudaEventRecord(evStart, 0);
    cudaStreamWaitEvent(s2, evStart, 0);
    round_w<<<1184, 256, 0, s2>>>(w1, w1r, (size_t)HIDN * NN1 / 4);
    cudaEventRecord(evW1, s2);
    gemm_tf32<1><<<dim3(4, 24), 256, 0, s2>>>(ref_latent, wk_ip, bk_ip, REFN, HIDN, HIDN);
    gemm_tf32<2><<<dim3(4, 24), 256, 0, s2>>>(ref_latent, wv_ip, bv_ip, REFN, HIDN, HIDN);
    refprep<<<dim3(24, REFN), 128, 0, s2>>>(ref_kn_w, ref_cos, ref_sin);
    cudaEventRecord(evRef, s2);
    round_w<<<1184, 256, 0, s2>>>(w2, w2r, (size_t)CATN * HIDN / 4);
    cudaEventRecord(evW2, s2);

    // main stream: mod chain + layernorm overlap the w1 pre-round
    mod_gemv<<<dim3(36, 8), 256>>>(vec, w_mod);
    mod_reduce<<<36, 256>>>(b_mod);
    ln_mod_kernel<<<LTOT, 256>>>(x);
    cudaStreamWaitEvent(0, evW1, 0);
    gemm_lin1<<<dim3(18, 84), 256, DSMEM_G0>>>(b1, LTOT, NN1, HIDN);
    qkvprep<<<dim3(24, LTOT), 128>>>(qn_w, kn_w, cosp, sinp);
    cudaStreamWaitEvent(0, evRef, 0);
    flash_fused<<<dim3(24, 18), 256, DSMEM_F>>>();
    cudaStreamWaitEvent(0, evW2, 0);
    gemm_out<<<dim3(18, 24), 256, DSMEM_G3>>>(b2, out, x, LTOT, HIDN, CATN);
}